// round 2
// baseline (speedup 1.0000x reference)
#include <cuda_runtime.h>
#include <cuda_fp16.h>

#define NB 32
#define NN 1024
#define NM 1024
#define CSH 2.7725887222397811f   /* ln(16) */

// K' = 16*exp(-D/eps) as fp16 (64 MB), W' = K'*D as fp16 (64 MB).
__device__ uint2 g_K[(size_t)NB * NN * NM / 4];
__device__ uint2 g_W[(size_t)NB * NN * NM / 4];
__device__ float g_u[NB * NN];          // u_i from the latest row phase
__device__ float g_t[3][NB * NM];       // col-sum triple buffer

// ---------------------------------------------------------------------------
// Convert: K' = exp(ln16 - 10D) (fp16), W' = fp16(K')*D (fp16).
// Also t[0]=1 (v0), t[1]=0 (first col target), out=0.
// ---------------------------------------------------------------------------
__global__ __launch_bounds__(256) void k_convert(const float4* __restrict__ D4,
                                                 float* __restrict__ out) {
    int idx = blockIdx.x * 256 + threadIdx.x;      // 0 .. 8388607
    float4 d = D4[idx];
    __half ka = __float2half_rn(__expf(fmaf(d.x, -10.0f, CSH)));
    __half kb = __float2half_rn(__expf(fmaf(d.y, -10.0f, CSH)));
    __half kc = __float2half_rn(__expf(fmaf(d.z, -10.0f, CSH)));
    __half kd = __float2half_rn(__expf(fmaf(d.w, -10.0f, CSH)));
    __half2 k0 = __halves2half2(ka, kb);
    __half2 k1 = __halves2half2(kc, kd);
    uint2 kp;
    kp.x = *reinterpret_cast<unsigned int*>(&k0);
    kp.y = *reinterpret_cast<unsigned int*>(&k1);
    g_K[idx] = kp;

    __half2 w0 = __floats2half2_rn(__half2float(ka) * d.x, __half2float(kb) * d.y);
    __half2 w1 = __floats2half2_rn(__half2float(kc) * d.z, __half2float(kd) * d.w);
    uint2 wp;
    wp.x = *reinterpret_cast<unsigned int*>(&w0);
    wp.y = *reinterpret_cast<unsigned int*>(&w1);
    g_W[idx] = wp;

    if (idx < NB * NM) { g_t[0][idx] = 1.0f; g_t[1][idx] = 0.0f; }
    if (idx == 0) *out = 0.0f;
}

// ---------------------------------------------------------------------------
// Fused Sinkhorn iteration: one pass over K'.
//   v = 1/tIn;  per row: s = sum_j K v_j, u = 1/s (stored);  tOut_j += K_ij u_i.
// grid: 1024 blocks x 256 threads (8 warps). Block owns 32 rows of one batch;
// warp owns 4 rows, keeps each row's K in regs for the col-accumulate reuse.
// Per-lane float4 acc over its 32 owned columns; smem-staged 8-warp merge;
// 4 REDG per thread (1024 per block) flush to tOut.
// ---------------------------------------------------------------------------
__global__ __launch_bounds__(256, 3) void k_iter(int k) {
    const float* __restrict__ tIn = g_t[k % 3];
    float* __restrict__ tOut = g_t[(k + 1) % 3];
    float* __restrict__ tZero = g_t[(k + 2) % 3];

    __shared__ float4 sv[NM / 4];          // 4 KB: v = 1/t
    __shared__ float4 stage[8][NM / 4];    // 32 KB: per-warp col partials

    int tid  = threadIdx.x;
    int w    = tid >> 5, lane = tid & 31;
    int b    = blockIdx.x >> 5;            // 32 blocks per batch
    int row0 = blockIdx.x * 32;

    if (tid < 32) tZero[blockIdx.x * 32 + tid] = 0.0f;   // 1024*32 = 32768

    float4 t4 = reinterpret_cast<const float4*>(tIn)[b * (NM / 4) + tid];
    sv[tid] = make_float4(1.0f / t4.x, 1.0f / t4.y, 1.0f / t4.z, 1.0f / t4.w);
    __syncthreads();

    float4 acc[8];
#pragma unroll
    for (int it = 0; it < 8; ++it) acc[it] = make_float4(0.f, 0.f, 0.f, 0.f);

#pragma unroll
    for (int c = 0; c < 4; ++c) {
        int row = row0 + w * 4 + c;
        const uint2* __restrict__ Kr = g_K + (size_t)row * (NM / 4);

        uint2 kk[8];
#pragma unroll
        for (int it = 0; it < 8; ++it) kk[it] = Kr[lane + it * 32];

        float s = 0.0f;
#pragma unroll
        for (int it = 0; it < 8; ++it) {
            float2 f0 = __half22float2(*reinterpret_cast<__half2*>(&kk[it].x));
            float2 f1 = __half22float2(*reinterpret_cast<__half2*>(&kk[it].y));
            float4 v = sv[lane + it * 32];
            s = fmaf(f0.x, v.x, s);
            s = fmaf(f0.y, v.y, s);
            s = fmaf(f1.x, v.z, s);
            s = fmaf(f1.y, v.w, s);
        }
#pragma unroll
        for (int o = 16; o > 0; o >>= 1) s += __shfl_xor_sync(0xffffffffu, s, o);
        float u = 1.0f / s;
        if (lane == 0) g_u[row] = u;

#pragma unroll
        for (int it = 0; it < 8; ++it) {
            float2 f0 = __half22float2(*reinterpret_cast<__half2*>(&kk[it].x));
            float2 f1 = __half22float2(*reinterpret_cast<__half2*>(&kk[it].y));
            acc[it].x = fmaf(f0.x, u, acc[it].x);
            acc[it].y = fmaf(f0.y, u, acc[it].y);
            acc[it].z = fmaf(f1.x, u, acc[it].z);
            acc[it].w = fmaf(f1.y, u, acc[it].w);
        }
    }

    // Stage per-warp column partials, then 8-way merge by 256 threads.
#pragma unroll
    for (int it = 0; it < 8; ++it) stage[w][lane + it * 32] = acc[it];
    __syncthreads();

    float4 r = stage[0][tid];
#pragma unroll
    for (int ww = 1; ww < 8; ++ww) {
        float4 x = stage[ww][tid];
        r.x += x.x; r.y += x.y; r.z += x.z; r.w += x.w;
    }
    float* to = tOut + b * NM + tid * 4;
    atomicAdd(to + 0, r.x);
    atomicAdd(to + 1, r.y);
    atomicAdd(to + 2, r.z);
    atomicAdd(to + 3, r.w);
}

// ---------------------------------------------------------------------------
// Final: loss = (1/NB) * sum_ij u_i * v_j * W'_ij   (W' = K'*D, u = g_u,
// v = 1/t from the 20th col phase = g_t[2]).
// grid: 4096 x 256, warp per row, one atomicAdd per block.
// ---------------------------------------------------------------------------
__global__ __launch_bounds__(256) void k_final(float* __restrict__ out) {
    const float* __restrict__ tIn = g_t[2];   // (19+1) % 3 == 2
    __shared__ float4 sv[NM / 4];
    __shared__ float part[8];

    int tid   = threadIdx.x;
    int grow0 = blockIdx.x * 8;
    int b     = grow0 >> 10;

    float4 t4 = reinterpret_cast<const float4*>(tIn)[b * (NM / 4) + tid];
    sv[tid] = make_float4(1.0f / t4.x, 1.0f / t4.y, 1.0f / t4.z, 1.0f / t4.w);
    __syncthreads();

    int warp = tid >> 5, lane = tid & 31;
    int row  = grow0 + warp;
    const uint2* __restrict__ Wr = g_W + (size_t)row * (NM / 4);

    float acc = 0.0f;
#pragma unroll
    for (int it = 0; it < 8; ++it) {
        int q = lane + it * 32;
        uint2 p = Wr[q];
        float2 f0 = __half22float2(*reinterpret_cast<__half2*>(&p.x));
        float2 f1 = __half22float2(*reinterpret_cast<__half2*>(&p.y));
        float4 v = sv[q];
        acc = fmaf(f0.x, v.x, acc);
        acc = fmaf(f0.y, v.y, acc);
        acc = fmaf(f1.x, v.z, acc);
        acc = fmaf(f1.y, v.w, acc);
    }
#pragma unroll
    for (int o = 16; o > 0; o >>= 1) acc += __shfl_xor_sync(0xffffffffu, acc, o);
    if (lane == 0) part[warp] = acc * g_u[row];
    __syncthreads();
    if (tid == 0) {
        float s2 = 0.0f;
#pragma unroll
        for (int w = 0; w < 8; ++w) s2 += part[w];
        atomicAdd(out, s2 * (1.0f / (float)NB));
    }
}

// ---------------------------------------------------------------------------
extern "C" void kernel_launch(void* const* d_in, const int* in_sizes, int n_in,
                              void* d_out, int out_size) {
    const float4* D4 = reinterpret_cast<const float4*>(d_in[0]);
    float* out = reinterpret_cast<float*>(d_out);

    k_convert<<<32768, 256>>>(D4, out);
    for (int k = 0; k < 20; ++k)
        k_iter<<<1024, 256>>>(k);
    k_final<<<4096, 256>>>(out);
}

// round 3
// speedup vs baseline: 1.3396x; 1.3396x over previous
#include <cuda_runtime.h>
#include <cuda_fp16.h>

#define NB 32
#define NN 1024
#define NM 1024
#define CSH 2.7725887222397811f   /* ln(16) */

// K' = 16*exp(-D/eps) as fp16 (64 MB, L2-resident), W' = K'*D as fp16 (64 MB).
__device__ uint2 g_K[(size_t)NB * NN * NM / 4];
__device__ uint2 g_W[(size_t)NB * NN * NM / 4];
__device__ float g_s[NB * NN];        // row sums  s_i = sum_j K v_j
__device__ float g_t0[NB * NM];       // ping-pong col sums
__device__ float g_t1[NB * NM];

// ---------------------------------------------------------------------------
// Convert: K' = exp(ln16 - 10D) (fp16), W' = fp16(K')*D (fp16).
// Also t0 = 1 (v0 = 1), out = 0.
// ---------------------------------------------------------------------------
__global__ __launch_bounds__(256) void k_convert(const float4* __restrict__ D4,
                                                 float* __restrict__ out) {
    int idx = blockIdx.x * 256 + threadIdx.x;      // 0 .. 8388607
    float4 d = D4[idx];
    __half ka = __float2half_rn(__expf(fmaf(d.x, -10.0f, CSH)));
    __half kb = __float2half_rn(__expf(fmaf(d.y, -10.0f, CSH)));
    __half kc = __float2half_rn(__expf(fmaf(d.z, -10.0f, CSH)));
    __half kd = __float2half_rn(__expf(fmaf(d.w, -10.0f, CSH)));
    __half2 k0 = __halves2half2(ka, kb);
    __half2 k1 = __halves2half2(kc, kd);
    uint2 kp;
    kp.x = *reinterpret_cast<unsigned int*>(&k0);
    kp.y = *reinterpret_cast<unsigned int*>(&k1);
    g_K[idx] = kp;

    __half2 w0 = __floats2half2_rn(__half2float(ka) * d.x, __half2float(kb) * d.y);
    __half2 w1 = __floats2half2_rn(__half2float(kc) * d.z, __half2float(kd) * d.w);
    uint2 wp;
    wp.x = *reinterpret_cast<unsigned int*>(&w0);
    wp.y = *reinterpret_cast<unsigned int*>(&w1);
    g_W[idx] = wp;

    if (idx < NB * NM) g_t0[idx] = 1.0f;
    if (idx == 0) *out = 0.0f;
}

// ---------------------------------------------------------------------------
// Row pass: s_i = sum_j K_ij * v_j, v_j = 1/tIn_j. Also zeroes tOut for the
// col pass that follows (ping-pong buffer last read one iteration ago — safe).
// grid: 4096 x 256; warp per row.  regs ~32, occ ~82%.
// ---------------------------------------------------------------------------
__global__ __launch_bounds__(256) void k_row(int parity) {
    const float* __restrict__ tIn  = parity ? g_t1 : g_t0;
    float* __restrict__       tOut = parity ? g_t0 : g_t1;
    __shared__ float4 sv[NM / 4];

    int tid   = threadIdx.x;
    int grow0 = blockIdx.x * 8;          // first global row of this block
    int b     = grow0 >> 10;             // batch (8 rows never cross a batch)

    if (tid < 8) tOut[blockIdx.x * 8 + tid] = 0.0f;   // 4096*8 = 32768 ✓

    float4 t4 = reinterpret_cast<const float4*>(tIn)[b * (NM / 4) + tid];
    sv[tid] = make_float4(1.0f / t4.x, 1.0f / t4.y, 1.0f / t4.z, 1.0f / t4.w);
    __syncthreads();

    int warp = tid >> 5, lane = tid & 31;
    int row  = grow0 + warp;
    const uint2* __restrict__ Kr = g_K + (size_t)row * (NM / 4);

    float acc = 0.0f;
#pragma unroll
    for (int it = 0; it < 8; ++it) {
        int q = lane + it * 32;
        uint2 p = Kr[q];
        float2 f0 = __half22float2(*reinterpret_cast<__half2*>(&p.x));
        float2 f1 = __half22float2(*reinterpret_cast<__half2*>(&p.y));
        float4 v = sv[q];
        acc = fmaf(f0.x, v.x, acc);
        acc = fmaf(f0.y, v.y, acc);
        acc = fmaf(f1.x, v.z, acc);
        acc = fmaf(f1.y, v.w, acc);
    }
#pragma unroll
    for (int o = 16; o > 0; o >>= 1) acc += __shfl_xor_sync(0xffffffffu, acc, o);
    if (lane == 0) g_s[row] = acc;
}

// ---------------------------------------------------------------------------
// Col pass: tOut_j += sum_i K_ij * u_i over a 64-row chunk, u_i = 1/s_i.
// grid: 512 (32 batches x 16 chunks) x 256; thread owns 4 consecutive cols,
// local accumulate, one atomicAdd x4.
// ---------------------------------------------------------------------------
__global__ __launch_bounds__(256) void k_col(int parity) {
    float* __restrict__ tOut = parity ? g_t0 : g_t1;
    __shared__ float su[64];

    int tid = threadIdx.x;
    int b   = blockIdx.x >> 4;
    int i0  = (blockIdx.x & 15) * 64;

    if (tid < 64) su[tid] = 1.0f / g_s[b * NN + i0 + tid];
    __syncthreads();

    const uint2* __restrict__ Kb = g_K + ((size_t)(b * NN + i0)) * (NM / 4) + tid;

    float4 acc = make_float4(0.f, 0.f, 0.f, 0.f);
#pragma unroll 4
    for (int i = 0; i < 64; ++i) {
        float u = su[i];
        uint2 p = Kb[(size_t)i * (NM / 4)];
        float2 f0 = __half22float2(*reinterpret_cast<__half2*>(&p.x));
        float2 f1 = __half22float2(*reinterpret_cast<__half2*>(&p.y));
        acc.x = fmaf(f0.x, u, acc.x);
        acc.y = fmaf(f0.y, u, acc.y);
        acc.z = fmaf(f1.x, u, acc.z);
        acc.w = fmaf(f1.y, u, acc.w);
    }
    float* to = tOut + b * NM + tid * 4;
    atomicAdd(to + 0, acc.x);
    atomicAdd(to + 1, acc.y);
    atomicAdd(to + 2, acc.z);
    atomicAdd(to + 3, acc.w);
}

// ---------------------------------------------------------------------------
// Final: loss = (1/NB) * sum_ij u_i * v_j * W'_ij   (W' = K'*D).
// u_i = 1/g_s[i] from the 20th row pass; v = 1/g_t0 (20th col pass, parity 1).
// grid: 4096 x 256; warp per row; one atomicAdd per block.
// ---------------------------------------------------------------------------
__global__ __launch_bounds__(256) void k_final(float* __restrict__ out) {
    const float* __restrict__ tIn = g_t0;   // last iteration k=19, parity 1 -> tOut = g_t0
    __shared__ float4 sv[NM / 4];
    __shared__ float part[8];

    int tid   = threadIdx.x;
    int grow0 = blockIdx.x * 8;
    int b     = grow0 >> 10;

    float4 t4 = reinterpret_cast<const float4*>(tIn)[b * (NM / 4) + tid];
    sv[tid] = make_float4(1.0f / t4.x, 1.0f / t4.y, 1.0f / t4.z, 1.0f / t4.w);
    __syncthreads();

    int warp = tid >> 5, lane = tid & 31;
    int row  = grow0 + warp;
    const uint2* __restrict__ Wr = g_W + (size_t)row * (NM / 4);

    float acc = 0.0f;
#pragma unroll
    for (int it = 0; it < 8; ++it) {
        int q = lane + it * 32;
        uint2 p = Wr[q];
        float2 f0 = __half22float2(*reinterpret_cast<__half2*>(&p.x));
        float2 f1 = __half22float2(*reinterpret_cast<__half2*>(&p.y));
        float4 v = sv[q];
        acc = fmaf(f0.x, v.x, acc);
        acc = fmaf(f0.y, v.y, acc);
        acc = fmaf(f1.x, v.z, acc);
        acc = fmaf(f1.y, v.w, acc);
    }
#pragma unroll
    for (int o = 16; o > 0; o >>= 1) acc += __shfl_xor_sync(0xffffffffu, acc, o);
    if (lane == 0) part[warp] = acc / g_s[row];
    __syncthreads();
    if (tid == 0) {
        float s2 = 0.0f;
#pragma unroll
        for (int w = 0; w < 8; ++w) s2 += part[w];
        atomicAdd(out, s2 * (1.0f / (float)NB));
    }
}

// ---------------------------------------------------------------------------
extern "C" void kernel_launch(void* const* d_in, const int* in_sizes, int n_in,
                              void* d_out, int out_size) {
    const float4* D4 = reinterpret_cast<const float4*>(d_in[0]);
    float* out = reinterpret_cast<float*>(d_out);

    k_convert<<<32768, 256>>>(D4, out);
    for (int k = 0; k < 20; ++k) {
        int parity = k & 1;           // tIn = parity ? t1 : t0, tOut = other
        k_row<<<4096, 256>>>(parity);
        k_col<<<512, 256>>>(parity);
    }
    k_final<<<4096, 256>>>(out);
}